// round 1
// baseline (speedup 1.0000x reference)
#include <cuda_runtime.h>
#include <cuda_bf16.h>
#include <math.h>

// ---------------------------------------------------------------------------
// Swin Transformer block (shifted-window attention + MLP), fp32 baseline.
// B=32, H=W=56, C=192, NH=6, HEAD_D=32, WS=7, SS=3, N=49, NW=64, HID=768
// M = B*NW*N = 100352 token rows.
// ---------------------------------------------------------------------------

#define MTOK   100352
#define CCH    192
#define NHEAD  6
#define HEADD  32
#define WSZ    7
#define NTOK   49
#define NWIN   64
#define HIDD   768
#define QKVC   576

// Scratch (allocation-free: __device__ globals)
__device__ float g_xw  [MTOK * CCH];   // LN'd shifted windowed tokens / later proj out
__device__ float g_big [MTOK * HIDD];  // qkv (uses 576 cols) / later MLP hidden (768)
__device__ float g_attn[MTOK * CCH];   // attention out / later LN2 out
__device__ float g_x2  [MTOK * CCH];   // residual after attention

__device__ __forceinline__ float warp_sum(float v) {
#pragma unroll
    for (int o = 16; o; o >>= 1) v += __shfl_xor_sync(0xffffffffu, v, o);
    return v;
}

// ---------------------------------------------------------------------------
// Kernel 1: LN1 + cyclic shift (-3,-3) + window partition. One warp per token.
// ---------------------------------------------------------------------------
__global__ void ln_shift_gather_kernel(const float* __restrict__ x,
                                       const float* __restrict__ g1,
                                       const float* __restrict__ b1) {
    int m = (blockIdx.x * blockDim.x + threadIdx.x) >> 5;
    int lane = threadIdx.x & 31;
    if (m >= MTOK) return;

    int wb  = m / NTOK;         // window-batch index [0, 2048)
    int n   = m - wb * NTOK;    // token within window
    int bi  = wb >> 6;          // image
    int win = wb & 63;
    int hs = (win >> 3) * WSZ + n / WSZ;   // shifted coords
    int ws = (win & 7)  * WSZ + n % WSZ;
    int hh = hs + 3; if (hh >= 56) hh -= 56;   // undo roll(-3): src = (shifted+3)%56
    int ww = ws + 3; if (ww >= 56) ww -= 56;

    const float* src = x + ((size_t)bi * 3136 + hh * 56 + ww) * CCH;
    float v[6];
    float s = 0.f;
#pragma unroll
    for (int i = 0; i < 6; i++) { v[i] = src[lane + 32 * i]; s += v[i]; }
    s = warp_sum(s);
    float mu = s * (1.0f / CCH);
    float q = 0.f;
#pragma unroll
    for (int i = 0; i < 6; i++) { float d = v[i] - mu; q += d * d; }
    q = warp_sum(q);
    float rstd = rsqrtf(q * (1.0f / CCH) + 1e-5f);

    float* dst = g_xw + (size_t)m * CCH;
#pragma unroll
    for (int i = 0; i < 6; i++) {
        int c = lane + 32 * i;
        dst[c] = (v[i] - mu) * rstd * g1[c] + b1[c];
    }
}

// ---------------------------------------------------------------------------
// Generic SGEMM: C[M,N] = A[M,K] @ W[N,K]^T + bias, with epilogue.
// BM=BN=64, BK=16, 256 threads, 4x4 microtiles. M%64==0, N%64==0, K%16==0.
// EPI: 0 = bias, 1 = bias + exact GELU, 2 = bias + residual add
// ---------------------------------------------------------------------------
template <int EPI>
__global__ void sgemm_kernel(const float* __restrict__ A,
                             const float* __restrict__ W,
                             const float* __restrict__ bias,
                             float* __restrict__ C,
                             const float* __restrict__ res,
                             int M, int N, int K) {
    const int BM = 64, BN = 64, BK = 16;
    __shared__ float As[BK][BM + 4];
    __shared__ float Ws[BK][BN + 4];

    int tid = threadIdx.x;            // 256
    int tx = tid & 15, ty = tid >> 4;
    int bm = blockIdx.y * BM, bn = blockIdx.x * BN;

    // loader mapping: each thread loads one float4 per tile per matrix
    int lr  = tid >> 2;               // 0..63 row in tile
    int lk4 = (tid & 3) << 2;         // 0,4,8,12
    const float* Aptr = A + (size_t)(bm + lr) * K + lk4;
    const float* Wptr = W + (size_t)(bn + lr) * K + lk4;

    float acc[4][4];
#pragma unroll
    for (int i = 0; i < 4; i++)
#pragma unroll
        for (int j = 0; j < 4; j++) acc[i][j] = 0.f;

    for (int k0 = 0; k0 < K; k0 += BK) {
        float4 av = *(const float4*)(Aptr + k0);
        float4 wv = *(const float4*)(Wptr + k0);
        As[lk4 + 0][lr] = av.x; As[lk4 + 1][lr] = av.y;
        As[lk4 + 2][lr] = av.z; As[lk4 + 3][lr] = av.w;
        Ws[lk4 + 0][lr] = wv.x; Ws[lk4 + 1][lr] = wv.y;
        Ws[lk4 + 2][lr] = wv.z; Ws[lk4 + 3][lr] = wv.w;
        __syncthreads();
#pragma unroll
        for (int kk = 0; kk < BK; kk++) {
            float4 a = *(const float4*)&As[kk][ty << 2];
            float4 b = *(const float4*)&Ws[kk][tx << 2];
            float ar[4] = {a.x, a.y, a.z, a.w};
            float br[4] = {b.x, b.y, b.z, b.w};
#pragma unroll
            for (int i = 0; i < 4; i++)
#pragma unroll
                for (int j = 0; j < 4; j++) acc[i][j] += ar[i] * br[j];
        }
        __syncthreads();
    }

#pragma unroll
    for (int i = 0; i < 4; i++) {
        int row = bm + (ty << 2) + i;
#pragma unroll
        for (int j = 0; j < 4; j++) {
            int col = bn + (tx << 2) + j;
            float v = acc[i][j] + bias[col];
            if (EPI == 1) v = 0.5f * v * (1.0f + erff(v * 0.70710678118654752f));
            if (EPI == 2) v += res[(size_t)row * N + col];
            C[(size_t)row * N + col] = v;
        }
    }
}

// ---------------------------------------------------------------------------
// Kernel 3: windowed attention. One block per (window-batch, head), 128 thr.
// ---------------------------------------------------------------------------
__global__ void attn_kernel(const float* __restrict__ bias_table) {
    int wb = blockIdx.x;   // 0..2047
    int h  = blockIdx.y;   // 0..5
    __shared__ float qs[NTOK * HEADD];
    __shared__ float ks[NTOK * HEADD];
    __shared__ float vs[NTOK * HEADD];
    __shared__ float sc[NTOK * NTOK];
    __shared__ int   rid[NTOK];

    int tid = threadIdx.x;   // 128
    const float scale = 0.17677669529663687f;   // 1/sqrt(32)

    const float* qkv = g_big;   // [MTOK, 576]
    size_t base = (size_t)wb * NTOK * QKVC + h * HEADD;
    for (int e = tid; e < NTOK * HEADD; e += 128) {
        int n = e >> 5, d = e & 31;
        size_t gidx = base + (size_t)n * QKVC + d;
        qs[e] = qkv[gidx] * scale;
        ks[e] = qkv[gidx + CCH];
        vs[e] = qkv[gidx + 2 * CCH];
    }
    if (tid < NTOK) {
        int win = wb & 63;
        int hh = (win >> 3) * WSZ + tid / WSZ;     // shifted coords of token
        int ww = (win & 7)  * WSZ + tid % WSZ;
        int rh = hh < 49 ? 0 : (hh < 53 ? 1 : 2);
        int rw = ww < 49 ? 0 : (ww < 53 ? 1 : 2);
        rid[tid] = rh * 3 + rw;
    }
    __syncthreads();

    // scores + rel-pos bias + shift mask
    for (int e = tid; e < NTOK * NTOK; e += 128) {
        int i = e / NTOK, j = e - i * NTOK;
        const float* qp = qs + i * HEADD;
        const float* kp = ks + j * HEADD;
        float s = 0.f;
#pragma unroll
        for (int d = 0; d < HEADD; d++) s += qp[d] * kp[d];
        int ri = i / 7 - j / 7 + 6;
        int ci = i % 7 - j % 7 + 6;
        s += bias_table[(ri * 13 + ci) * NHEAD + h];
        if (rid[i] != rid[j]) s -= 100.0f;
        sc[e] = s;
    }
    __syncthreads();

    // softmax: warp per row
    int warp = tid >> 5, lane = tid & 31;
    for (int r = warp; r < NTOK; r += 4) {
        float* row = sc + r * NTOK;
        float mx = -1e30f;
        for (int j = lane; j < NTOK; j += 32) mx = fmaxf(mx, row[j]);
#pragma unroll
        for (int o = 16; o; o >>= 1) mx = fmaxf(mx, __shfl_xor_sync(0xffffffffu, mx, o));
        float s = 0.f;
        for (int j = lane; j < NTOK; j += 32) { float e2 = __expf(row[j] - mx); row[j] = e2; s += e2; }
#pragma unroll
        for (int o = 16; o; o >>= 1) s += __shfl_xor_sync(0xffffffffu, s, o);
        float inv = 1.0f / s;
        for (int j = lane; j < NTOK; j += 32) row[j] *= inv;
    }
    __syncthreads();

    // out = attn @ v -> g_attn[(wb*49+n)*192 + h*32 + d]
    size_t obase = (size_t)wb * NTOK * CCH + h * HEADD;
    for (int e = tid; e < NTOK * HEADD; e += 128) {
        int n = e >> 5, d = e & 31;
        const float* pr = sc + n * NTOK;
        float s = 0.f;
#pragma unroll
        for (int m2 = 0; m2 < NTOK; m2++) s += pr[m2] * vs[m2 * HEADD + d];
        g_attn[obase + (size_t)n * CCH + d] = s;
    }
}

// ---------------------------------------------------------------------------
// Kernel 4: window reverse + unshift + residual add + LN2. One warp/token.
// proj output is in g_xw (windowed order); writes g_x2 (residual) and
// g_attn (LN2 output) in original token order.
// ---------------------------------------------------------------------------
__global__ void reverse_add_ln2_kernel(const float* __restrict__ x,
                                       const float* __restrict__ g2,
                                       const float* __restrict__ b2) {
    int m = (blockIdx.x * blockDim.x + threadIdx.x) >> 5;
    int lane = threadIdx.x & 31;
    if (m >= MTOK) return;

    int wb  = m / NTOK;
    int n   = m - wb * NTOK;
    int bi  = wb >> 6;
    int win = wb & 63;
    int hs = (win >> 3) * WSZ + n / WSZ;
    int ws = (win & 7)  * WSZ + n % WSZ;
    int hh = hs + 3; if (hh >= 56) hh -= 56;
    int ww = ws + 3; if (ww >= 56) ww -= 56;
    size_t t = (size_t)bi * 3136 + hh * 56 + ww;   // original token index

    const float* xs = x + t * CCH;
    const float* pr = g_xw + (size_t)m * CCH;
    float* x2 = g_x2 + t * CCH;
    float* hl = g_attn + t * CCH;

    float v[6];
    float s = 0.f;
#pragma unroll
    for (int i = 0; i < 6; i++) {
        int c = lane + 32 * i;
        v[i] = xs[c] + pr[c];
        x2[c] = v[i];
        s += v[i];
    }
    s = warp_sum(s);
    float mu = s * (1.0f / CCH);
    float q = 0.f;
#pragma unroll
    for (int i = 0; i < 6; i++) { float d = v[i] - mu; q += d * d; }
    q = warp_sum(q);
    float rstd = rsqrtf(q * (1.0f / CCH) + 1e-5f);
#pragma unroll
    for (int i = 0; i < 6; i++) {
        int c = lane + 32 * i;
        hl[c] = (v[i] - mu) * rstd * g2[c] + b2[c];
    }
}

// ---------------------------------------------------------------------------
// Host launcher
// ---------------------------------------------------------------------------
extern "C" void kernel_launch(void* const* d_in, const int* in_sizes, int n_in,
                              void* d_out, int out_size) {
    const float* x          = (const float*)d_in[0];
    const float* g1         = (const float*)d_in[1];
    const float* b1         = (const float*)d_in[2];
    const float* qkv_w      = (const float*)d_in[3];
    const float* qkv_b      = (const float*)d_in[4];
    const float* proj_w     = (const float*)d_in[5];
    const float* proj_b     = (const float*)d_in[6];
    const float* bias_table = (const float*)d_in[7];
    const float* g2         = (const float*)d_in[8];
    const float* b2         = (const float*)d_in[9];
    const float* fc1_w      = (const float*)d_in[10];
    const float* fc1_b      = (const float*)d_in[11];
    const float* fc2_w      = (const float*)d_in[12];
    const float* fc2_b      = (const float*)d_in[13];
    float* out = (float*)d_out;

    float *p_xw, *p_big, *p_attn, *p_x2;
    cudaGetSymbolAddress((void**)&p_xw,   g_xw);
    cudaGetSymbolAddress((void**)&p_big,  g_big);
    cudaGetSymbolAddress((void**)&p_attn, g_attn);
    cudaGetSymbolAddress((void**)&p_x2,   g_x2);

    // 1. LN1 + shift + partition  -> g_xw [M,192]
    ln_shift_gather_kernel<<<MTOK / 8, 256>>>(x, g1, b1);

    // 2. qkv = xw @ qkv_w^T + b   -> g_big [M,576]
    sgemm_kernel<0><<<dim3(QKVC / 64, MTOK / 64), 256>>>(
        p_xw, qkv_w, qkv_b, p_big, nullptr, MTOK, QKVC, CCH);

    // 3. windowed attention       -> g_attn [M,192]
    attn_kernel<<<dim3(MTOK / NTOK, NHEAD), 128>>>(bias_table);

    // 4. proj                     -> g_xw [M,192]
    sgemm_kernel<0><<<dim3(CCH / 64, MTOK / 64), 256>>>(
        p_attn, proj_w, proj_b, p_xw, nullptr, MTOK, CCH, CCH);

    // 5. reverse + unshift + residual + LN2 -> g_x2, g_attn(=LN2 out)
    reverse_add_ln2_kernel<<<MTOK / 8, 256>>>(x, g2, b2);

    // 6. fc1 + GELU               -> g_big [M,768]
    sgemm_kernel<1><<<dim3(HIDD / 64, MTOK / 64), 256>>>(
        p_attn, fc1_w, fc1_b, p_big, nullptr, MTOK, HIDD, CCH);

    // 7. fc2 + residual(g_x2)     -> d_out [M,192]
    sgemm_kernel<2><<<dim3(CCH / 64, MTOK / 64), 256>>>(
        p_big, fc2_w, fc2_b, out, p_x2, MTOK, CCH, HIDD);
}

// round 2
// speedup vs baseline: 1.4040x; 1.4040x over previous
#include <cuda_runtime.h>
#include <cuda_bf16.h>
#include <math.h>

// ---------------------------------------------------------------------------
// Swin Transformer block, Round 2: tf32 tensor-core GEMMs (mma.sync m16n8k8).
// B=32, H=W=56, C=192, NH=6, HEAD_D=32, WS=7, SS=3, N=49, NW=64, HID=768
// ---------------------------------------------------------------------------

#define MTOK   100352
#define CCH    192
#define NHEAD  6
#define HEADD  32
#define WSZ    7
#define NTOK   49
#define NWIN   64
#define HIDD   768
#define QKVC   576

__device__ float g_xw  [MTOK * CCH];
__device__ float g_big [MTOK * HIDD];
__device__ float g_attn[MTOK * CCH];
__device__ float g_x2  [MTOK * CCH];

__device__ __forceinline__ float warp_sum(float v) {
#pragma unroll
    for (int o = 16; o; o >>= 1) v += __shfl_xor_sync(0xffffffffu, v, o);
    return v;
}

__device__ __forceinline__ unsigned f2tf32(float f) {
    unsigned u;
    asm("cvt.rna.tf32.f32 %0, %1;" : "=r"(u) : "f"(f));
    return u;
}

// ---------------------------------------------------------------------------
// Kernel 1: LN1 + cyclic shift (-3,-3) + window partition. One warp per token.
// ---------------------------------------------------------------------------
__global__ void ln_shift_gather_kernel(const float* __restrict__ x,
                                       const float* __restrict__ g1,
                                       const float* __restrict__ b1) {
    int m = (blockIdx.x * blockDim.x + threadIdx.x) >> 5;
    int lane = threadIdx.x & 31;
    if (m >= MTOK) return;

    int wb  = m / NTOK;
    int n   = m - wb * NTOK;
    int bi  = wb >> 6;
    int win = wb & 63;
    int hs = (win >> 3) * WSZ + n / WSZ;
    int ws = (win & 7)  * WSZ + n % WSZ;
    int hh = hs + 3; if (hh >= 56) hh -= 56;
    int ww = ws + 3; if (ww >= 56) ww -= 56;

    const float* src = x + ((size_t)bi * 3136 + hh * 56 + ww) * CCH;
    float v[6];
    float s = 0.f;
#pragma unroll
    for (int i = 0; i < 6; i++) { v[i] = src[lane + 32 * i]; s += v[i]; }
    s = warp_sum(s);
    float mu = s * (1.0f / CCH);
    float q = 0.f;
#pragma unroll
    for (int i = 0; i < 6; i++) { float d = v[i] - mu; q += d * d; }
    q = warp_sum(q);
    float rstd = rsqrtf(q * (1.0f / CCH) + 1e-5f);

    float* dst = g_xw + (size_t)m * CCH;
#pragma unroll
    for (int i = 0; i < 6; i++) {
        int c = lane + 32 * i;
        dst[c] = (v[i] - mu) * rstd * g1[c] + b1[c];
    }
}

// ---------------------------------------------------------------------------
// tf32 tensor-core GEMM: C[M,N] = A[M,K] @ W[N,K]^T + bias (+epilogue)
// BM=128, BN=64, BK=32, 256 threads = 8 warps (4 M x 2 N), 32x32 warp tiles.
// Requires M%128==0, N%64==0, K%32==0.
// EPI: 0 = bias, 1 = bias + exact GELU, 2 = bias + residual add
// ---------------------------------------------------------------------------
template <int EPI>
__global__ __launch_bounds__(256) void tc_gemm_kernel(
        const float* __restrict__ A,
        const float* __restrict__ W,
        const float* __restrict__ bias,
        float* __restrict__ C,
        const float* __restrict__ res,
        int M, int N, int K) {
    const int BM = 128, BN = 64, BK = 32;
    __shared__ unsigned As[BK][BM + 4];   // k-major, tf32 bits
    __shared__ unsigned Ws[BK][BN + 4];

    int t = threadIdx.x;
    int bm = blockIdx.y * BM, bn = blockIdx.x * BN;

    int warp = t >> 5, lane = t & 31;
    int wm = (warp & 3) * 32;        // warp M offset in tile
    int wn = (warp >> 2) * 32;       // warp N offset in tile
    int qr = lane >> 2, qc = lane & 3;

    // loader mapping
    int lr = t >> 3;                 // 0..31
    int lc = (t & 7) << 2;           // 0,4,...,28
    const float* Ap = A + (size_t)(bm + lr) * K + lc;
    const float* Wp = W + (size_t)(bn + lr) * K + lc;

    float acc[2][4][4];
#pragma unroll
    for (int i = 0; i < 2; i++)
#pragma unroll
        for (int j = 0; j < 4; j++)
#pragma unroll
            for (int e = 0; e < 4; e++) acc[i][j][e] = 0.f;

    for (int k0 = 0; k0 < K; k0 += BK) {
        // load A tile: rows lr, lr+32, lr+64, lr+96
#pragma unroll
        for (int i = 0; i < 4; i++) {
            float4 v = *(const float4*)(Ap + k0 + (size_t)(32 * i) * K);
            As[lc + 0][lr + 32 * i] = f2tf32(v.x);
            As[lc + 1][lr + 32 * i] = f2tf32(v.y);
            As[lc + 2][lr + 32 * i] = f2tf32(v.z);
            As[lc + 3][lr + 32 * i] = f2tf32(v.w);
        }
        // load W tile: rows lr, lr+32
#pragma unroll
        for (int i = 0; i < 2; i++) {
            float4 v = *(const float4*)(Wp + k0 + (size_t)(32 * i) * K);
            Ws[lc + 0][lr + 32 * i] = f2tf32(v.x);
            Ws[lc + 1][lr + 32 * i] = f2tf32(v.y);
            Ws[lc + 2][lr + 32 * i] = f2tf32(v.z);
            Ws[lc + 3][lr + 32 * i] = f2tf32(v.w);
        }
        __syncthreads();

#pragma unroll
        for (int k8 = 0; k8 < 4; k8++) {
            int kk = k8 * 8;
            unsigned a[2][4], b[4][2];
#pragma unroll
            for (int mi = 0; mi < 2; mi++) {
                int r = wm + mi * 16 + qr;
                a[mi][0] = As[kk + qc    ][r];
                a[mi][1] = As[kk + qc    ][r + 8];
                a[mi][2] = As[kk + qc + 4][r];
                a[mi][3] = As[kk + qc + 4][r + 8];
            }
#pragma unroll
            for (int ni = 0; ni < 4; ni++) {
                int c = wn + ni * 8 + qr;
                b[ni][0] = Ws[kk + qc    ][c];
                b[ni][1] = Ws[kk + qc + 4][c];
            }
#pragma unroll
            for (int mi = 0; mi < 2; mi++)
#pragma unroll
                for (int ni = 0; ni < 4; ni++) {
                    asm volatile(
                        "mma.sync.aligned.m16n8k8.row.col.f32.tf32.tf32.f32 "
                        "{%0,%1,%2,%3}, {%4,%5,%6,%7}, {%8,%9}, {%0,%1,%2,%3};"
                        : "+f"(acc[mi][ni][0]), "+f"(acc[mi][ni][1]),
                          "+f"(acc[mi][ni][2]), "+f"(acc[mi][ni][3])
                        : "r"(a[mi][0]), "r"(a[mi][1]), "r"(a[mi][2]), "r"(a[mi][3]),
                          "r"(b[ni][0]), "r"(b[ni][1]));
                }
        }
        __syncthreads();
    }

    // epilogue: c0:(r,c) c1:(r,c+1) c2:(r+8,c) c3:(r+8,c+1)
#pragma unroll
    for (int mi = 0; mi < 2; mi++) {
#pragma unroll
        for (int ni = 0; ni < 4; ni++) {
            int row = bm + wm + mi * 16 + qr;
            int col = bn + wn + ni * 8 + qc * 2;
#pragma unroll
            for (int e = 0; e < 4; e++) {
                int r = row + (e >> 1) * 8;
                int c = col + (e & 1);
                float v = acc[mi][ni][e] + bias[c];
                if (EPI == 1) v = 0.5f * v * (1.0f + erff(v * 0.70710678118654752f));
                if (EPI == 2) v += res[(size_t)r * N + c];
                C[(size_t)r * N + c] = v;
            }
        }
    }
}

// ---------------------------------------------------------------------------
// Kernel 3: windowed attention. One block per (window-batch, head), 128 thr.
// ---------------------------------------------------------------------------
__global__ void attn_kernel(const float* __restrict__ bias_table) {
    int wb = blockIdx.x;
    int h  = blockIdx.y;
    __shared__ float qs[NTOK * HEADD];
    __shared__ float ks[NTOK * HEADD];
    __shared__ float vs[NTOK * HEADD];
    __shared__ float sc[NTOK * NTOK];
    __shared__ int   rid[NTOK];

    int tid = threadIdx.x;
    const float scale = 0.17677669529663687f;

    const float* qkv = g_big;
    size_t base = (size_t)wb * NTOK * QKVC + h * HEADD;
    for (int e = tid; e < NTOK * HEADD; e += 128) {
        int n = e >> 5, d = e & 31;
        size_t gidx = base + (size_t)n * QKVC + d;
        qs[e] = qkv[gidx] * scale;
        ks[e] = qkv[gidx + CCH];
        vs[e] = qkv[gidx + 2 * CCH];
    }
    if (tid < NTOK) {
        int win = wb & 63;
        int hh = (win >> 3) * WSZ + tid / WSZ;
        int ww = (win & 7)  * WSZ + tid % WSZ;
        int rh = hh < 49 ? 0 : (hh < 53 ? 1 : 2);
        int rw = ww < 49 ? 0 : (ww < 53 ? 1 : 2);
        rid[tid] = rh * 3 + rw;
    }
    __syncthreads();

    for (int e = tid; e < NTOK * NTOK; e += 128) {
        int i = e / NTOK, j = e - i * NTOK;
        const float* qp = qs + i * HEADD;
        const float* kp = ks + j * HEADD;
        float s = 0.f;
#pragma unroll
        for (int d = 0; d < HEADD; d++) s += qp[d] * kp[d];
        int ri = i / 7 - j / 7 + 6;
        int ci = i % 7 - j % 7 + 6;
        s += bias_table[(ri * 13 + ci) * NHEAD + h];
        if (rid[i] != rid[j]) s -= 100.0f;
        sc[e] = s;
    }
    __syncthreads();

    int warp = tid >> 5, lane = tid & 31;
    for (int r = warp; r < NTOK; r += 4) {
        float* row = sc + r * NTOK;
        float mx = -1e30f;
        for (int j = lane; j < NTOK; j += 32) mx = fmaxf(mx, row[j]);
#pragma unroll
        for (int o = 16; o; o >>= 1) mx = fmaxf(mx, __shfl_xor_sync(0xffffffffu, mx, o));
        float s = 0.f;
        for (int j = lane; j < NTOK; j += 32) { float e2 = __expf(row[j] - mx); row[j] = e2; s += e2; }
#pragma unroll
        for (int o = 16; o; o >>= 1) s += __shfl_xor_sync(0xffffffffu, s, o);
        float inv = 1.0f / s;
        for (int j = lane; j < NTOK; j += 32) row[j] *= inv;
    }
    __syncthreads();

    size_t obase = (size_t)wb * NTOK * CCH + h * HEADD;
    for (int e = tid; e < NTOK * HEADD; e += 128) {
        int n = e >> 5, d = e & 31;
        const float* pr = sc + n * NTOK;
        float s = 0.f;
#pragma unroll
        for (int m2 = 0; m2 < NTOK; m2++) s += pr[m2] * vs[m2 * HEADD + d];
        g_attn[obase + (size_t)n * CCH + d] = s;
    }
}

// ---------------------------------------------------------------------------
// Kernel 4: window reverse + unshift + residual add + LN2. One warp/token.
// ---------------------------------------------------------------------------
__global__ void reverse_add_ln2_kernel(const float* __restrict__ x,
                                       const float* __restrict__ g2,
                                       const float* __restrict__ b2) {
    int m = (blockIdx.x * blockDim.x + threadIdx.x) >> 5;
    int lane = threadIdx.x & 31;
    if (m >= MTOK) return;

    int wb  = m / NTOK;
    int n   = m - wb * NTOK;
    int bi  = wb >> 6;
    int win = wb & 63;
    int hs = (win >> 3) * WSZ + n / WSZ;
    int ws = (win & 7)  * WSZ + n % WSZ;
    int hh = hs + 3; if (hh >= 56) hh -= 56;
    int ww = ws + 3; if (ww >= 56) ww -= 56;
    size_t tt = (size_t)bi * 3136 + hh * 56 + ww;

    const float* xs = x + tt * CCH;
    const float* pr = g_xw + (size_t)m * CCH;
    float* x2 = g_x2 + tt * CCH;
    float* hl = g_attn + tt * CCH;

    float v[6];
    float s = 0.f;
#pragma unroll
    for (int i = 0; i < 6; i++) {
        int c = lane + 32 * i;
        v[i] = xs[c] + pr[c];
        x2[c] = v[i];
        s += v[i];
    }
    s = warp_sum(s);
    float mu = s * (1.0f / CCH);
    float q = 0.f;
#pragma unroll
    for (int i = 0; i < 6; i++) { float d = v[i] - mu; q += d * d; }
    q = warp_sum(q);
    float rstd = rsqrtf(q * (1.0f / CCH) + 1e-5f);
#pragma unroll
    for (int i = 0; i < 6; i++) {
        int c = lane + 32 * i;
        hl[c] = (v[i] - mu) * rstd * g2[c] + b2[c];
    }
}

// ---------------------------------------------------------------------------
// Host launcher
// ---------------------------------------------------------------------------
extern "C" void kernel_launch(void* const* d_in, const int* in_sizes, int n_in,
                              void* d_out, int out_size) {
    const float* x          = (const float*)d_in[0];
    const float* g1         = (const float*)d_in[1];
    const float* b1         = (const float*)d_in[2];
    const float* qkv_w      = (const float*)d_in[3];
    const float* qkv_b      = (const float*)d_in[4];
    const float* proj_w     = (const float*)d_in[5];
    const float* proj_b     = (const float*)d_in[6];
    const float* bias_table = (const float*)d_in[7];
    const float* g2         = (const float*)d_in[8];
    const float* b2         = (const float*)d_in[9];
    const float* fc1_w      = (const float*)d_in[10];
    const float* fc1_b      = (const float*)d_in[11];
    const float* fc2_w      = (const float*)d_in[12];
    const float* fc2_b      = (const float*)d_in[13];
    float* out = (float*)d_out;

    float *p_xw, *p_big, *p_attn, *p_x2;
    cudaGetSymbolAddress((void**)&p_xw,   g_xw);
    cudaGetSymbolAddress((void**)&p_big,  g_big);
    cudaGetSymbolAddress((void**)&p_attn, g_attn);
    cudaGetSymbolAddress((void**)&p_x2,   g_x2);

    // 1. LN1 + shift + partition  -> g_xw [M,192]
    ln_shift_gather_kernel<<<MTOK / 8, 256>>>(x, g1, b1);

    // 2. qkv = xw @ qkv_w^T + b   -> g_big [M,576]
    tc_gemm_kernel<0><<<dim3(QKVC / 64, MTOK / 128), 256>>>(
        p_xw, qkv_w, qkv_b, p_big, nullptr, MTOK, QKVC, CCH);

    // 3. windowed attention       -> g_attn [M,192]
    attn_kernel<<<dim3(MTOK / NTOK, NHEAD), 128>>>(bias_table);

    // 4. proj                     -> g_xw [M,192]
    tc_gemm_kernel<0><<<dim3(CCH / 64, MTOK / 128), 256>>>(
        p_attn, proj_w, proj_b, p_xw, nullptr, MTOK, CCH, CCH);

    // 5. reverse + unshift + residual + LN2 -> g_x2, g_attn(=LN2 out)
    reverse_add_ln2_kernel<<<MTOK / 8, 256>>>(x, g2, b2);

    // 6. fc1 + GELU               -> g_big [M,768]
    tc_gemm_kernel<1><<<dim3(HIDD / 64, MTOK / 128), 256>>>(
        p_attn, fc1_w, fc1_b, p_big, nullptr, MTOK, HIDD, CCH);

    // 7. fc2 + residual(g_x2)     -> d_out [M,192]
    tc_gemm_kernel<2><<<dim3(CCH / 64, MTOK / 128), 256>>>(
        p_big, fc2_w, fc2_b, out, p_x2, MTOK, CCH, HIDD);
}

// round 4
// speedup vs baseline: 1.9491x; 1.3882x over previous
#include <cuda_runtime.h>
#include <cuda_bf16.h>
#include <cstdint>
#include <math.h>

// ---------------------------------------------------------------------------
// Swin block, Round 4: bf16 m16n8k16 mma + ldmatrix + cp.async double buffer.
// (Round 3 design; fixed missing integer-type declarations.)
// ---------------------------------------------------------------------------

#define MTOK   100352
#define CCH    192
#define NHEAD  6
#define HEADD  32
#define WSZ    7
#define NTOK   49
#define HIDD   768
#define QKVC   576

typedef __nv_bfloat16 bf16;
typedef unsigned int u32;

// Scratch
__device__ bf16  g_ln1 [MTOK * CCH];
__device__ bf16  g_qkv [MTOK * QKVC];
__device__ bf16  g_att [MTOK * CCH];
__device__ float g_proj[MTOK * CCH];
__device__ float g_x2  [MTOK * CCH];
__device__ bf16  g_ln2 [MTOK * CCH];
__device__ bf16  g_hid [MTOK * HIDD];
__device__ bf16  g_wq  [QKVC * CCH];
__device__ bf16  g_wp  [CCH * CCH];
__device__ bf16  g_w1  [HIDD * CCH];
__device__ bf16  g_w2  [CCH * HIDD];

__device__ __forceinline__ float warp_sum(float v) {
#pragma unroll
    for (int o = 16; o; o >>= 1) v += __shfl_xor_sync(0xffffffffu, v, o);
    return v;
}

__device__ __forceinline__ u32 smem_u32(const void* p) {
    u32 a;
    asm("{ .reg .u64 t; cvta.to.shared.u64 t, %1; cvt.u32.u64 %0, t; }"
        : "=r"(a) : "l"(p));
    return a;
}

__device__ __forceinline__ void ldsm4(u32& r0, u32& r1, u32& r2, u32& r3, u32 a) {
    asm volatile("ldmatrix.sync.aligned.m8n8.x4.shared.b16 {%0,%1,%2,%3},[%4];"
                 : "=r"(r0), "=r"(r1), "=r"(r2), "=r"(r3) : "r"(a));
}

__device__ __forceinline__ void cp16(u32 dst, const void* src) {
    asm volatile("cp.async.cg.shared.global [%0],[%1],16;" :: "r"(dst), "l"(src));
}

// ---------------------------------------------------------------------------
// Kernel 0: weights fp32 -> bf16
// ---------------------------------------------------------------------------
__global__ void convert_weights(const float* __restrict__ qw,
                                const float* __restrict__ pw,
                                const float* __restrict__ w1,
                                const float* __restrict__ w2) {
    int i = blockIdx.x * 256 + threadIdx.x;
    if (i < QKVC * CCH) g_wq[i] = __float2bfloat16(qw[i]);
    if (i < CCH * CCH)  g_wp[i] = __float2bfloat16(pw[i]);
    if (i < HIDD * CCH) g_w1[i] = __float2bfloat16(w1[i]);
    if (i < CCH * HIDD) g_w2[i] = __float2bfloat16(w2[i]);
}

// ---------------------------------------------------------------------------
// Kernel 1: LN1 + cyclic shift + window partition -> bf16. One warp per token.
// ---------------------------------------------------------------------------
__global__ void ln_shift_gather_kernel(const float* __restrict__ x,
                                       const float* __restrict__ g1,
                                       const float* __restrict__ b1) {
    int m = (blockIdx.x * blockDim.x + threadIdx.x) >> 5;
    int lane = threadIdx.x & 31;
    if (m >= MTOK) return;

    int wb  = m / NTOK;
    int n   = m - wb * NTOK;
    int bi  = wb >> 6;
    int win = wb & 63;
    int hs = (win >> 3) * WSZ + n / WSZ;
    int ws = (win & 7)  * WSZ + n % WSZ;
    int hh = hs + 3; if (hh >= 56) hh -= 56;
    int ww = ws + 3; if (ww >= 56) ww -= 56;

    const float* src = x + ((size_t)bi * 3136 + hh * 56 + ww) * CCH;
    float v[6];
    float s = 0.f;
#pragma unroll
    for (int i = 0; i < 6; i++) { v[i] = src[lane + 32 * i]; s += v[i]; }
    s = warp_sum(s);
    float mu = s * (1.0f / CCH);
    float q = 0.f;
#pragma unroll
    for (int i = 0; i < 6; i++) { float d = v[i] - mu; q += d * d; }
    q = warp_sum(q);
    float rstd = rsqrtf(q * (1.0f / CCH) + 1e-5f);

    bf16* dst = g_ln1 + (size_t)m * CCH;
#pragma unroll
    for (int i = 0; i < 6; i++) {
        int c = lane + 32 * i;
        dst[c] = __float2bfloat16((v[i] - mu) * rstd * g1[c] + b1[c]);
    }
}

// ---------------------------------------------------------------------------
// bf16 tensor-core GEMM: C[M,N] = A[M,K] @ W[N,K]^T + bias (+epilogue)
// BM=128 BN=64 BK=32, 256 threads (8 warps 4x2), warp tile 32x32.
// ldmatrix fragments, cp.async double-buffered. M%128==0, N%64==0, K%32==0.
// EPI: 0 bias->OutT, 1 bias+GELU->OutT, 2 bias+res(fp32)->OutT
// ---------------------------------------------------------------------------
template <int EPI, typename OutT>
__global__ __launch_bounds__(256) void bf16_gemm_kernel(
        const bf16* __restrict__ A,
        const bf16* __restrict__ W,
        const float* __restrict__ bias,
        OutT* __restrict__ C,
        const float* __restrict__ res,
        int M, int N, int K) {
    const int BM = 128, BN = 64, BK = 32, LDA = 40;     // halves; 80B rows
    const int STAGE_H = (BM + BN) * LDA;                // halves per stage
    __shared__ bf16 smem[2 * STAGE_H];

    int t = threadIdx.x;
    int bm = blockIdx.y * BM, bn = blockIdx.x * BN;
    int warp = t >> 5, lane = t & 31;
    int wm = (warp & 3) * 32, wn = (warp >> 2) * 32;
    int qr = lane >> 2, qc = lane & 3;

    u32 sbase = smem_u32(smem);

    // loader mapping
    int arow = t >> 1, ac = (t & 1) * 2;     // A: 2 chunks (16B) per thread
    int brow = t >> 2, bc = t & 3;           // B: 1 chunk per thread
    const bf16* Ag = A + (size_t)(bm + arow) * K + ac * 8;
    const bf16* Wg = W + (size_t)(bn + brow) * K + bc * 8;
    u32 adst = sbase + (arow * LDA + ac * 8) * 2;
    u32 bdst = sbase + ((BM + brow) * LDA + bc * 8) * 2;

    // ldmatrix per-lane source offsets (bytes, within stage)
    int l15 = lane & 15, lhi = lane >> 4;
    u32 aoff = ((wm + l15) * LDA + lhi * 8) * 2;              // + mi*16*LDA*2 + kb
    int bl = (lane & 7) + ((lane & 16) ? 8 : 0);
    int bkc = (lane >> 3) & 1;
    u32 boff = ((BM + wn + bl) * LDA + bkc * 8) * 2;          // + p*16*LDA*2 + kb

    float acc[2][4][4];
#pragma unroll
    for (int i = 0; i < 2; i++)
#pragma unroll
        for (int j = 0; j < 4; j++)
#pragma unroll
            for (int e = 0; e < 4; e++) acc[i][j][e] = 0.f;

    const u32 STB = STAGE_H * 2;   // stage bytes
    int nk = K / BK;

    // prologue: stage 0
    cp16(adst, Ag);
    cp16(adst + 16, Ag + 8);
    cp16(bdst, Wg);
    asm volatile("cp.async.commit_group;" ::: "memory");

    for (int i = 0; i < nk; i++) {
        asm volatile("cp.async.wait_group 0;" ::: "memory");
        __syncthreads();
        if (i + 1 < nk) {
            u32 so = ((i + 1) & 1) * STB;
            int k0 = (i + 1) * BK;
            cp16(adst + so, Ag + k0);
            cp16(adst + so + 16, Ag + k0 + 8);
            cp16(bdst + so, Wg + k0);
            asm volatile("cp.async.commit_group;" ::: "memory");
        }
        u32 so = (i & 1) * STB;
#pragma unroll
        for (int kk = 0; kk < 2; kk++) {
            u32 kb = kk * 32;   // 16 halves
            u32 a0, a1, a2, a3, a4, a5, a6, a7;
            ldsm4(a0, a1, a2, a3, sbase + so + aoff + kb);
            ldsm4(a4, a5, a6, a7, sbase + so + aoff + 16 * LDA * 2 + kb);
            u32 b[4][2];
            ldsm4(b[0][0], b[0][1], b[1][0], b[1][1], sbase + so + boff + kb);
            ldsm4(b[2][0], b[2][1], b[3][0], b[3][1],
                  sbase + so + boff + 16 * LDA * 2 + kb);
            u32 am[2][4] = {{a0, a1, a2, a3}, {a4, a5, a6, a7}};
#pragma unroll
            for (int mi = 0; mi < 2; mi++)
#pragma unroll
                for (int ni = 0; ni < 4; ni++) {
                    asm volatile(
                        "mma.sync.aligned.m16n8k16.row.col.f32.bf16.bf16.f32 "
                        "{%0,%1,%2,%3},{%4,%5,%6,%7},{%8,%9},{%0,%1,%2,%3};"
                        : "+f"(acc[mi][ni][0]), "+f"(acc[mi][ni][1]),
                          "+f"(acc[mi][ni][2]), "+f"(acc[mi][ni][3])
                        : "r"(am[mi][0]), "r"(am[mi][1]),
                          "r"(am[mi][2]), "r"(am[mi][3]),
                          "r"(b[ni][0]), "r"(b[ni][1]));
                }
        }
        __syncthreads();
    }

    // epilogue: c0:(r,c) c1:(r,c+1) c2:(r+8,c) c3:(r+8,c+1)
#pragma unroll
    for (int mi = 0; mi < 2; mi++) {
#pragma unroll
        for (int ni = 0; ni < 4; ni++) {
            int row = bm + wm + mi * 16 + qr;
            int col = bn + wn + ni * 8 + qc * 2;
#pragma unroll
            for (int e = 0; e < 4; e++) {
                int r = row + (e >> 1) * 8;
                int c = col + (e & 1);
                float v = acc[mi][ni][e] + bias[c];
                if (EPI == 1) v = 0.5f * v * (1.0f + erff(v * 0.70710678118654752f));
                if (EPI == 2) v += res[(size_t)r * N + c];
                if (sizeof(OutT) == 2)
                    C[(size_t)r * N + c] = (OutT)__float2bfloat16(v);
                else
                    C[(size_t)r * N + c] = (OutT)v;
            }
        }
    }
}

// ---------------------------------------------------------------------------
// Kernel 3: windowed attention (bf16 IO). One block per (window, head).
// ---------------------------------------------------------------------------
__global__ void attn_kernel(const float* __restrict__ bias_table) {
    int wb = blockIdx.x;
    int h  = blockIdx.y;
    __shared__ float qs[NTOK * HEADD];
    __shared__ float ks[NTOK * HEADD];
    __shared__ float vs[NTOK * HEADD];
    __shared__ float sc[NTOK * NTOK];
    __shared__ int   rid[NTOK];

    int tid = threadIdx.x;
    const float scale = 0.17677669529663687f;

    size_t base = (size_t)wb * NTOK * QKVC + h * HEADD;
    for (int e = tid; e < NTOK * HEADD; e += 128) {
        int n = e >> 5, d = e & 31;
        size_t gidx = base + (size_t)n * QKVC + d;
        qs[e] = __bfloat162float(g_qkv[gidx]) * scale;
        ks[e] = __bfloat162float(g_qkv[gidx + CCH]);
        vs[e] = __bfloat162float(g_qkv[gidx + 2 * CCH]);
    }
    if (tid < NTOK) {
        int win = wb & 63;
        int hh = (win >> 3) * WSZ + tid / WSZ;
        int ww = (win & 7)  * WSZ + tid % WSZ;
        int rh = hh < 49 ? 0 : (hh < 53 ? 1 : 2);
        int rw = ww < 49 ? 0 : (ww < 53 ? 1 : 2);
        rid[tid] = rh * 3 + rw;
    }
    __syncthreads();

    for (int e = tid; e < NTOK * NTOK; e += 128) {
        int i = e / NTOK, j = e - i * NTOK;
        const float* qp = qs + i * HEADD;
        const float* kp = ks + j * HEADD;
        float s = 0.f;
#pragma unroll
        for (int d = 0; d < HEADD; d++) s += qp[d] * kp[d];
        int ri = i / 7 - j / 7 + 6;
        int ci = i % 7 - j % 7 + 6;
        s += bias_table[(ri * 13 + ci) * NHEAD + h];
        if (rid[i] != rid[j]) s -= 100.0f;
        sc[e] = s;
    }
    __syncthreads();

    int warp = tid >> 5, lane = tid & 31;
    for (int r = warp; r < NTOK; r += 4) {
        float* row = sc + r * NTOK;
        float mx = -1e30f;
        for (int j = lane; j < NTOK; j += 32) mx = fmaxf(mx, row[j]);
#pragma unroll
        for (int o = 16; o; o >>= 1) mx = fmaxf(mx, __shfl_xor_sync(0xffffffffu, mx, o));
        float s = 0.f;
        for (int j = lane; j < NTOK; j += 32) { float e2 = __expf(row[j] - mx); row[j] = e2; s += e2; }
#pragma unroll
        for (int o = 16; o; o >>= 1) s += __shfl_xor_sync(0xffffffffu, s, o);
        float inv = 1.0f / s;
        for (int j = lane; j < NTOK; j += 32) row[j] *= inv;
    }
    __syncthreads();

    size_t obase = (size_t)wb * NTOK * CCH + h * HEADD;
    for (int e = tid; e < NTOK * HEADD; e += 128) {
        int n = e >> 5, d = e & 31;
        const float* pr = sc + n * NTOK;
        float s = 0.f;
#pragma unroll
        for (int m2 = 0; m2 < NTOK; m2++) s += pr[m2] * vs[m2 * HEADD + d];
        g_att[obase + (size_t)n * CCH + d] = __float2bfloat16(s);
    }
}

// ---------------------------------------------------------------------------
// Kernel 4: window reverse + unshift + residual + LN2.
// ---------------------------------------------------------------------------
__global__ void reverse_add_ln2_kernel(const float* __restrict__ x,
                                       const float* __restrict__ g2,
                                       const float* __restrict__ b2) {
    int m = (blockIdx.x * blockDim.x + threadIdx.x) >> 5;
    int lane = threadIdx.x & 31;
    if (m >= MTOK) return;

    int wb  = m / NTOK;
    int n   = m - wb * NTOK;
    int bi  = wb >> 6;
    int win = wb & 63;
    int hs = (win >> 3) * WSZ + n / WSZ;
    int ws = (win & 7)  * WSZ + n % WSZ;
    int hh = hs + 3; if (hh >= 56) hh -= 56;
    int ww = ws + 3; if (ww >= 56) ww -= 56;
    size_t tt = (size_t)bi * 3136 + hh * 56 + ww;

    const float* xs = x + tt * CCH;
    const float* pr = g_proj + (size_t)m * CCH;
    float* x2 = g_x2 + tt * CCH;
    bf16* hl  = g_ln2 + tt * CCH;

    float v[6];
    float s = 0.f;
#pragma unroll
    for (int i = 0; i < 6; i++) {
        int c = lane + 32 * i;
        v[i] = xs[c] + pr[c];
        x2[c] = v[i];
        s += v[i];
    }
    s = warp_sum(s);
    float mu = s * (1.0f / CCH);
    float q = 0.f;
#pragma unroll
    for (int i = 0; i < 6; i++) { float d = v[i] - mu; q += d * d; }
    q = warp_sum(q);
    float rstd = rsqrtf(q * (1.0f / CCH) + 1e-5f);
#pragma unroll
    for (int i = 0; i < 6; i++) {
        int c = lane + 32 * i;
        hl[c] = __float2bfloat16((v[i] - mu) * rstd * g2[c] + b2[c]);
    }
}

// ---------------------------------------------------------------------------
// Host launcher
// ---------------------------------------------------------------------------
extern "C" void kernel_launch(void* const* d_in, const int* in_sizes, int n_in,
                              void* d_out, int out_size) {
    const float* x          = (const float*)d_in[0];
    const float* g1         = (const float*)d_in[1];
    const float* b1         = (const float*)d_in[2];
    const float* qkv_w      = (const float*)d_in[3];
    const float* qkv_b      = (const float*)d_in[4];
    const float* proj_w     = (const float*)d_in[5];
    const float* proj_b     = (const float*)d_in[6];
    const float* bias_table = (const float*)d_in[7];
    const float* g2         = (const float*)d_in[8];
    const float* b2         = (const float*)d_in[9];
    const float* fc1_w      = (const float*)d_in[10];
    const float* fc1_b      = (const float*)d_in[11];
    const float* fc2_w      = (const float*)d_in[12];
    const float* fc2_b      = (const float*)d_in[13];
    float* out = (float*)d_out;

    bf16 *p_ln1, *p_qkvb, *p_att, *p_ln2, *p_hid, *p_wq, *p_wp, *p_w1, *p_w2;
    float *p_proj, *p_x2;
    cudaGetSymbolAddress((void**)&p_ln1,  g_ln1);
    cudaGetSymbolAddress((void**)&p_qkvb, g_qkv);
    cudaGetSymbolAddress((void**)&p_att,  g_att);
    cudaGetSymbolAddress((void**)&p_proj, g_proj);
    cudaGetSymbolAddress((void**)&p_x2,   g_x2);
    cudaGetSymbolAddress((void**)&p_ln2,  g_ln2);
    cudaGetSymbolAddress((void**)&p_hid,  g_hid);
    cudaGetSymbolAddress((void**)&p_wq,   g_wq);
    cudaGetSymbolAddress((void**)&p_wp,   g_wp);
    cudaGetSymbolAddress((void**)&p_w1,   g_w1);
    cudaGetSymbolAddress((void**)&p_w2,   g_w2);

    convert_weights<<<576, 256>>>(qkv_w, proj_w, fc1_w, fc2_w);

    ln_shift_gather_kernel<<<MTOK / 8, 256>>>(x, g1, b1);

    bf16_gemm_kernel<0, bf16><<<dim3(QKVC / 64, MTOK / 128), 256>>>(
        p_ln1, p_wq, qkv_b, p_qkvb, nullptr, MTOK, QKVC, CCH);

    attn_kernel<<<dim3(MTOK / NTOK, NHEAD), 128>>>(bias_table);

    bf16_gemm_kernel<0, float><<<dim3(CCH / 64, MTOK / 128), 256>>>(
        p_att, p_wp, proj_b, p_proj, nullptr, MTOK, CCH, CCH);

    reverse_add_ln2_kernel<<<MTOK / 8, 256>>>(x, g2, b2);

    bf16_gemm_kernel<1, bf16><<<dim3(HIDD / 64, MTOK / 128), 256>>>(
        p_ln2, p_w1, fc1_b, p_hid, nullptr, MTOK, HIDD, CCH);

    bf16_gemm_kernel<2, float><<<dim3(CCH / 64, MTOK / 128), 256>>>(
        p_hid, p_w2, fc2_b, out, p_x2, MTOK, CCH, HIDD);
}

// round 5
// speedup vs baseline: 3.3229x; 1.7048x over previous
#include <cuda_runtime.h>
#include <cuda_bf16.h>
#include <cstdint>
#include <math.h>

// ---------------------------------------------------------------------------
// Swin block, Round 5: register-row attention + bf16 mma GEMMs.
// ---------------------------------------------------------------------------

#define MTOK   100352
#define CCH    192
#define NHEAD  6
#define HEADD  32
#define WSZ    7
#define NTOK   49
#define HIDD   768
#define QKVC   576

typedef __nv_bfloat16 bf16;
typedef unsigned int u32;

// Scratch
__device__ bf16  g_ln1 [MTOK * CCH];
__device__ bf16  g_qkv [MTOK * QKVC];
__device__ bf16  g_att [MTOK * CCH];
__device__ float g_proj[MTOK * CCH];
__device__ float g_x2  [MTOK * CCH];
__device__ bf16  g_ln2 [MTOK * CCH];
__device__ bf16  g_hid [MTOK * HIDD];
__device__ bf16  g_wq  [QKVC * CCH];
__device__ bf16  g_wp  [CCH * CCH];
__device__ bf16  g_w1  [HIDD * CCH];
__device__ bf16  g_w2  [CCH * HIDD];

__device__ __forceinline__ float warp_sum(float v) {
#pragma unroll
    for (int o = 16; o; o >>= 1) v += __shfl_xor_sync(0xffffffffu, v, o);
    return v;
}

__device__ __forceinline__ u32 smem_u32(const void* p) {
    u32 a;
    asm("{ .reg .u64 t; cvta.to.shared.u64 t, %1; cvt.u32.u64 %0, t; }"
        : "=r"(a) : "l"(p));
    return a;
}

__device__ __forceinline__ void ldsm4(u32& r0, u32& r1, u32& r2, u32& r3, u32 a) {
    asm volatile("ldmatrix.sync.aligned.m8n8.x4.shared.b16 {%0,%1,%2,%3},[%4];"
                 : "=r"(r0), "=r"(r1), "=r"(r2), "=r"(r3) : "r"(a));
}

__device__ __forceinline__ void cp16(u32 dst, const void* src) {
    asm volatile("cp.async.cg.shared.global [%0],[%1],16;" :: "r"(dst), "l"(src));
}

// ---------------------------------------------------------------------------
// Kernel 0: weights fp32 -> bf16
// ---------------------------------------------------------------------------
__global__ void convert_weights(const float* __restrict__ qw,
                                const float* __restrict__ pw,
                                const float* __restrict__ w1,
                                const float* __restrict__ w2) {
    int i = blockIdx.x * 256 + threadIdx.x;
    if (i < QKVC * CCH) g_wq[i] = __float2bfloat16(qw[i]);
    if (i < CCH * CCH)  g_wp[i] = __float2bfloat16(pw[i]);
    if (i < HIDD * CCH) g_w1[i] = __float2bfloat16(w1[i]);
    if (i < CCH * HIDD) g_w2[i] = __float2bfloat16(w2[i]);
}

// ---------------------------------------------------------------------------
// Kernel 1: LN1 + cyclic shift + window partition -> bf16. One warp per token.
// ---------------------------------------------------------------------------
__global__ void ln_shift_gather_kernel(const float* __restrict__ x,
                                       const float* __restrict__ g1,
                                       const float* __restrict__ b1) {
    int m = (blockIdx.x * blockDim.x + threadIdx.x) >> 5;
    int lane = threadIdx.x & 31;
    if (m >= MTOK) return;

    int wb  = m / NTOK;
    int n   = m - wb * NTOK;
    int bi  = wb >> 6;
    int win = wb & 63;
    int hs = (win >> 3) * WSZ + n / WSZ;
    int ws = (win & 7)  * WSZ + n % WSZ;
    int hh = hs + 3; if (hh >= 56) hh -= 56;
    int ww = ws + 3; if (ww >= 56) ww -= 56;

    const float* src = x + ((size_t)bi * 3136 + hh * 56 + ww) * CCH;
    float v[6];
    float s = 0.f;
#pragma unroll
    for (int i = 0; i < 6; i++) { v[i] = src[lane + 32 * i]; s += v[i]; }
    s = warp_sum(s);
    float mu = s * (1.0f / CCH);
    float q = 0.f;
#pragma unroll
    for (int i = 0; i < 6; i++) { float d = v[i] - mu; q += d * d; }
    q = warp_sum(q);
    float rstd = rsqrtf(q * (1.0f / CCH) + 1e-5f);

    bf16* dst = g_ln1 + (size_t)m * CCH;
#pragma unroll
    for (int i = 0; i < 6; i++) {
        int c = lane + 32 * i;
        dst[c] = __float2bfloat16((v[i] - mu) * rstd * g1[c] + b1[c]);
    }
}

// ---------------------------------------------------------------------------
// bf16 tensor-core GEMM: C[M,N] = A[M,K] @ W[N,K]^T + bias (+epilogue)
// ---------------------------------------------------------------------------
template <int EPI, typename OutT>
__global__ __launch_bounds__(256) void bf16_gemm_kernel(
        const bf16* __restrict__ A,
        const bf16* __restrict__ W,
        const float* __restrict__ bias,
        OutT* __restrict__ C,
        const float* __restrict__ res,
        int M, int N, int K) {
    const int BM = 128, BN = 64, BK = 32, LDA = 40;     // halves; 80B rows
    const int STAGE_H = (BM + BN) * LDA;
    __shared__ bf16 smem[2 * STAGE_H];

    int t = threadIdx.x;
    int bm = blockIdx.y * BM, bn = blockIdx.x * BN;
    int warp = t >> 5, lane = t & 31;
    int wm = (warp & 3) * 32, wn = (warp >> 2) * 32;
    int qr = lane >> 2, qc = lane & 3;

    u32 sbase = smem_u32(smem);

    int arow = t >> 1, ac = (t & 1) * 2;
    int brow = t >> 2, bc = t & 3;
    const bf16* Ag = A + (size_t)(bm + arow) * K + ac * 8;
    const bf16* Wg = W + (size_t)(bn + brow) * K + bc * 8;
    u32 adst = sbase + (arow * LDA + ac * 8) * 2;
    u32 bdst = sbase + ((BM + brow) * LDA + bc * 8) * 2;

    int l15 = lane & 15, lhi = lane >> 4;
    u32 aoff = ((wm + l15) * LDA + lhi * 8) * 2;
    int bl = (lane & 7) + ((lane & 16) ? 8 : 0);
    int bkc = (lane >> 3) & 1;
    u32 boff = ((BM + wn + bl) * LDA + bkc * 8) * 2;

    float acc[2][4][4];
#pragma unroll
    for (int i = 0; i < 2; i++)
#pragma unroll
        for (int j = 0; j < 4; j++)
#pragma unroll
            for (int e = 0; e < 4; e++) acc[i][j][e] = 0.f;

    const u32 STB = STAGE_H * 2;
    int nk = K / BK;

    cp16(adst, Ag);
    cp16(adst + 16, Ag + 8);
    cp16(bdst, Wg);
    asm volatile("cp.async.commit_group;" ::: "memory");

    for (int i = 0; i < nk; i++) {
        asm volatile("cp.async.wait_group 0;" ::: "memory");
        __syncthreads();
        if (i + 1 < nk) {
            u32 so = ((i + 1) & 1) * STB;
            int k0 = (i + 1) * BK;
            cp16(adst + so, Ag + k0);
            cp16(adst + so + 16, Ag + k0 + 8);
            cp16(bdst + so, Wg + k0);
            asm volatile("cp.async.commit_group;" ::: "memory");
        }
        u32 so = (i & 1) * STB;
#pragma unroll
        for (int kk = 0; kk < 2; kk++) {
            u32 kb = kk * 32;
            u32 a0, a1, a2, a3, a4, a5, a6, a7;
            ldsm4(a0, a1, a2, a3, sbase + so + aoff + kb);
            ldsm4(a4, a5, a6, a7, sbase + so + aoff + 16 * LDA * 2 + kb);
            u32 b[4][2];
            ldsm4(b[0][0], b[0][1], b[1][0], b[1][1], sbase + so + boff + kb);
            ldsm4(b[2][0], b[2][1], b[3][0], b[3][1],
                  sbase + so + boff + 16 * LDA * 2 + kb);
            u32 am[2][4] = {{a0, a1, a2, a3}, {a4, a5, a6, a7}};
#pragma unroll
            for (int mi = 0; mi < 2; mi++)
#pragma unroll
                for (int ni = 0; ni < 4; ni++) {
                    asm volatile(
                        "mma.sync.aligned.m16n8k16.row.col.f32.bf16.bf16.f32 "
                        "{%0,%1,%2,%3},{%4,%5,%6,%7},{%8,%9},{%0,%1,%2,%3};"
                        : "+f"(acc[mi][ni][0]), "+f"(acc[mi][ni][1]),
                          "+f"(acc[mi][ni][2]), "+f"(acc[mi][ni][3])
                        : "r"(am[mi][0]), "r"(am[mi][1]),
                          "r"(am[mi][2]), "r"(am[mi][3]),
                          "r"(b[ni][0]), "r"(b[ni][1]));
                }
        }
        __syncthreads();
    }

#pragma unroll
    for (int mi = 0; mi < 2; mi++) {
#pragma unroll
        for (int ni = 0; ni < 4; ni++) {
            int row = bm + wm + mi * 16 + qr;
            int col = bn + wn + ni * 8 + qc * 2;
#pragma unroll
            for (int e = 0; e < 4; e++) {
                int r = row + (e >> 1) * 8;
                int c = col + (e & 1);
                float v = acc[mi][ni][e] + bias[c];
                if (EPI == 1) v = 0.5f * v * (1.0f + erff(v * 0.70710678118654752f));
                if (EPI == 2) v += res[(size_t)r * N + c];
                if (sizeof(OutT) == 2)
                    C[(size_t)r * N + c] = (OutT)__float2bfloat16(v);
                else
                    C[(size_t)r * N + c] = (OutT)v;
            }
        }
    }
}

// ---------------------------------------------------------------------------
// Kernel 3: attention, one thread per query row. Block = (window, head), 64 thr.
// s[49] in registers; K/V in smem fp32 (broadcast float4 reads).
// ---------------------------------------------------------------------------
__global__ __launch_bounds__(64) void attn_kernel(const float* __restrict__ bias_table) {
    int wb = blockIdx.x;   // 0..2047
    int h  = blockIdx.y;   // 0..5
    __shared__ float kf[NTOK * HEADD];
    __shared__ float vf[NTOK * HEADD];
    __shared__ float bsm[169];
    __shared__ int   rid[NTOK];

    int tid = threadIdx.x;
    const float scale = 0.17677669529663687f;

    size_t base = (size_t)wb * NTOK * QKVC + h * HEADD;

    // cooperative K/V load: 784 bf16x2 units each
    for (int u = tid; u < NTOK * 16; u += 64) {
        int n = u >> 4, d2 = (u & 15) << 1;
        size_t gi = base + (size_t)n * QKVC + d2;
        __nv_bfloat162 kv = *(const __nv_bfloat162*)(g_qkv + gi + CCH);
        __nv_bfloat162 vv = *(const __nv_bfloat162*)(g_qkv + gi + 2 * CCH);
        kf[n * 32 + d2]     = __bfloat162float(kv.x);
        kf[n * 32 + d2 + 1] = __bfloat162float(kv.y);
        vf[n * 32 + d2]     = __bfloat162float(vv.x);
        vf[n * 32 + d2 + 1] = __bfloat162float(vv.y);
    }
    for (int u = tid; u < 169; u += 64) bsm[u] = bias_table[u * NHEAD + h];
    if (tid < NTOK) {
        int win = wb & 63;
        int hh = (win >> 3) * WSZ + tid / WSZ;
        int ww = (win & 7)  * WSZ + tid % WSZ;
        int rh = hh < 49 ? 0 : (hh < 53 ? 1 : 2);
        int rw = ww < 49 ? 0 : (ww < 53 ? 1 : 2);
        rid[tid] = rh * 3 + rw;
    }
    __syncthreads();

    if (tid >= NTOK) return;
    int i = tid;

    // q row -> registers (scaled)
    float q[32];
    const bf16* qp = g_qkv + base + (size_t)i * QKVC;
#pragma unroll
    for (int d2 = 0; d2 < 16; d2++) {
        __nv_bfloat162 t = *(const __nv_bfloat162*)(qp + 2 * d2);
        q[2 * d2]     = __bfloat162float(t.x) * scale;
        q[2 * d2 + 1] = __bfloat162float(t.y) * scale;
    }

    int ih = i / 7, iw = i % 7, myrid = rid[i];

    float s[NTOK];
#pragma unroll
    for (int j = 0; j < NTOK; j++) {
        const float4* kp = (const float4*)(kf + j * 32);
        float acc = 0.f;
#pragma unroll
        for (int c = 0; c < 8; c++) {
            float4 kv = kp[c];
            acc += q[4 * c] * kv.x + q[4 * c + 1] * kv.y
                 + q[4 * c + 2] * kv.z + q[4 * c + 3] * kv.w;
        }
        int jh = j / 7, jw = j % 7;
        acc += bsm[(ih - jh + 6) * 13 + (iw - jw + 6)];
        if (myrid != rid[j]) acc -= 100.0f;
        s[j] = acc;
    }

    // in-register softmax
    float mx = s[0];
#pragma unroll
    for (int j = 1; j < NTOK; j++) mx = fmaxf(mx, s[j]);
    float sum = 0.f;
#pragma unroll
    for (int j = 0; j < NTOK; j++) { s[j] = __expf(s[j] - mx); sum += s[j]; }
    float inv = 1.0f / sum;
#pragma unroll
    for (int j = 0; j < NTOK; j++) s[j] *= inv;

    // out = p @ V
    float o[32];
#pragma unroll
    for (int d = 0; d < 32; d++) o[d] = 0.f;
#pragma unroll
    for (int j = 0; j < NTOK; j++) {
        const float4* vp = (const float4*)(vf + j * 32);
        float pj = s[j];
#pragma unroll
        for (int c = 0; c < 8; c++) {
            float4 vv = vp[c];
            o[4 * c]     += pj * vv.x;
            o[4 * c + 1] += pj * vv.y;
            o[4 * c + 2] += pj * vv.z;
            o[4 * c + 3] += pj * vv.w;
        }
    }

    bf16* op = g_att + (size_t)(wb * NTOK + i) * CCH + h * HEADD;
#pragma unroll
    for (int d2 = 0; d2 < 16; d2++) {
        __nv_bfloat162 t;
        t.x = __float2bfloat16(o[2 * d2]);
        t.y = __float2bfloat16(o[2 * d2 + 1]);
        *(__nv_bfloat162*)(op + 2 * d2) = t;
    }
}

// ---------------------------------------------------------------------------
// Kernel 4: window reverse + unshift + residual + LN2.
// ---------------------------------------------------------------------------
__global__ void reverse_add_ln2_kernel(const float* __restrict__ x,
                                       const float* __restrict__ g2,
                                       const float* __restrict__ b2) {
    int m = (blockIdx.x * blockDim.x + threadIdx.x) >> 5;
    int lane = threadIdx.x & 31;
    if (m >= MTOK) return;

    int wb  = m / NTOK;
    int n   = m - wb * NTOK;
    int bi  = wb >> 6;
    int win = wb & 63;
    int hs = (win >> 3) * WSZ + n / WSZ;
    int ws = (win & 7)  * WSZ + n % WSZ;
    int hh = hs + 3; if (hh >= 56) hh -= 56;
    int ww = ws + 3; if (ww >= 56) ww -= 56;
    size_t tt = (size_t)bi * 3136 + hh * 56 + ww;

    const float* xs = x + tt * CCH;
    const float* pr = g_proj + (size_t)m * CCH;
    float* x2 = g_x2 + tt * CCH;
    bf16* hl  = g_ln2 + tt * CCH;

    float v[6];
    float s = 0.f;
#pragma unroll
    for (int i = 0; i < 6; i++) {
        int c = lane + 32 * i;
        v[i] = xs[c] + pr[c];
        x2[c] = v[i];
        s += v[i];
    }
    s = warp_sum(s);
    float mu = s * (1.0f / CCH);
    float q = 0.f;
#pragma unroll
    for (int i = 0; i < 6; i++) { float d = v[i] - mu; q += d * d; }
    q = warp_sum(q);
    float rstd = rsqrtf(q * (1.0f / CCH) + 1e-5f);
#pragma unroll
    for (int i = 0; i < 6; i++) {
        int c = lane + 32 * i;
        hl[c] = __float2bfloat16((v[i] - mu) * rstd * g2[c] + b2[c]);
    }
}

// ---------------------------------------------------------------------------
// Host launcher
// ---------------------------------------------------------------------------
extern "C" void kernel_launch(void* const* d_in, const int* in_sizes, int n_in,
                              void* d_out, int out_size) {
    const float* x          = (const float*)d_in[0];
    const float* g1         = (const float*)d_in[1];
    const float* b1         = (const float*)d_in[2];
    const float* qkv_w      = (const float*)d_in[3];
    const float* qkv_b      = (const float*)d_in[4];
    const float* proj_w     = (const float*)d_in[5];
    const float* proj_b     = (const float*)d_in[6];
    const float* bias_table = (const float*)d_in[7];
    const float* g2         = (const float*)d_in[8];
    const float* b2         = (const float*)d_in[9];
    const float* fc1_w      = (const float*)d_in[10];
    const float* fc1_b      = (const float*)d_in[11];
    const float* fc2_w      = (const float*)d_in[12];
    const float* fc2_b      = (const float*)d_in[13];
    float* out = (float*)d_out;

    bf16 *p_ln1, *p_qkvb, *p_att, *p_ln2, *p_hid, *p_wq, *p_wp, *p_w1, *p_w2;
    float *p_proj, *p_x2;
    cudaGetSymbolAddress((void**)&p_ln1,  g_ln1);
    cudaGetSymbolAddress((void**)&p_qkvb, g_qkv);
    cudaGetSymbolAddress((void**)&p_att,  g_att);
    cudaGetSymbolAddress((void**)&p_proj, g_proj);
    cudaGetSymbolAddress((void**)&p_x2,   g_x2);
    cudaGetSymbolAddress((void**)&p_ln2,  g_ln2);
    cudaGetSymbolAddress((void**)&p_hid,  g_hid);
    cudaGetSymbolAddress((void**)&p_wq,   g_wq);
    cudaGetSymbolAddress((void**)&p_wp,   g_wp);
    cudaGetSymbolAddress((void**)&p_w1,   g_w1);
    cudaGetSymbolAddress((void**)&p_w2,   g_w2);

    convert_weights<<<576, 256>>>(qkv_w, proj_w, fc1_w, fc2_w);

    ln_shift_gather_kernel<<<MTOK / 8, 256>>>(x, g1, b1);

    bf16_gemm_kernel<0, bf16><<<dim3(QKVC / 64, MTOK / 128), 256>>>(
        p_ln1, p_wq, qkv_b, p_qkvb, nullptr, MTOK, QKVC, CCH);

    attn_kernel<<<dim3(MTOK / NTOK, NHEAD), 64>>>(bias_table);

    bf16_gemm_kernel<0, float><<<dim3(CCH / 64, MTOK / 128), 256>>>(
        p_att, p_wp, proj_b, p_proj, nullptr, MTOK, CCH, CCH);

    reverse_add_ln2_kernel<<<MTOK / 8, 256>>>(x, g2, b2);

    bf16_gemm_kernel<1, bf16><<<dim3(HIDD / 64, MTOK / 128), 256>>>(
        p_ln2, p_w1, fc1_b, p_hid, nullptr, MTOK, HIDD, CCH);

    bf16_gemm_kernel<2, float><<<dim3(CCH / 64, MTOK / 128), 256>>>(
        p_hid, p_w2, fc2_b, out, p_x2, MTOK, CCH, HIDD);
}